// round 14
// baseline (speedup 1.0000x reference)
#include <cuda_runtime.h>
#include <math.h>

// Shapes (fixed by the problem)
#define NROWS   32768
#define INDIM   768
#define HIDDIM  1024
#define EMBD    256
#define KCOS    2048
#define KCL     50
#define KCLP    128     // cluster codebook padded to one 128-code tile

typedef unsigned long long u64;

// ---------------- packed f32x2 helpers (Blackwell 2x fp32 path) ----------------
__device__ __forceinline__ void fma2(u64& d, u64 a, u64 b){
    asm("fma.rn.f32x2 %0, %1, %2, %0;" : "+l"(d) : "l"(a), "l"(b));
}
__device__ __forceinline__ u64 pack2(float x){
    u64 r; asm("mov.b64 %0, {%1, %1};" : "=l"(r) : "f"(x)); return r;
}
__device__ __forceinline__ float2 unpack2(u64 v){
    float2 f; asm("mov.b64 {%0, %1}, %2;" : "=f"(f.x), "=f"(f.y) : "l"(v)); return f;
}
__device__ __forceinline__ float warp_sum(float s){
    #pragma unroll
    for (int o=16;o>0;o>>=1) s += __shfl_xor_sync(0xffffffffu, s, o);
    return s;
}

// ---------------- scratch: __device__ globals (no allocations allowed) ----------------
__device__ float g_h   [NROWS*HIDDIM];   // encoder hidden
__device__ float g_res [NROWS*EMBD];     // encoder output
__device__ float g_r1  [NROWS*EMBD];     // res - q_cluster
__device__ float g_r2  [NROWS*EMBD];     // r1 - q_cos0
__device__ float g_re  [NROWS*EMBD];     // res - (q_cos0+q_cos1)  (euclid input)
__device__ float g_rq  [NROWS*EMBD];     // running quantized (cos stages)
__device__ float g_cl_n[KCLP*EMBD];      // normalized cluster codes, row-major (gather)
__device__ float g_clT [EMBD*KCLP];      // transposed (sim B operand)
__device__ float g_bias_cl[KCLP];        // 0 for real codes, -1e30 for padding
__device__ float g_cos_n[2*KCOS*EMBD];   // normalized cosine codes, row-major
__device__ float g_cosT [2*EMBD*KCOS];   // transposed
__device__ float g_eucT [EMBD*KCOS];     // euclid codes transposed (raw)
__device__ float g_bias_euc[KCOS];       // -0.5*||c||^2
__device__ float g_bias_zero[KCOS];      // zeros
__device__ int   g_idx[4*NROWS];         // per-stage argmax indices
__device__ float g_losspart[4*1024];     // per-block loss partial sums

// ---------------- codebook prep: normalize (+transpose), biases ----------------
// one warp per code; grid covers 128 + 4096 + 2048 = 6272 warps
__global__ void prep_codes(const float* __restrict__ cbc,
                           const float* __restrict__ cbcos,
                           const float* __restrict__ cbe){
    int gt = blockIdx.x*blockDim.x + threadIdx.x;
    if (gt < KCOS) g_bias_zero[gt] = 0.f;
    int w = gt >> 5;
    int lane = threadIdx.x & 31;
    if (w < KCLP){
        int k = w;
        if (k < KCL){
            float v[8]; float s = 0.f;
            #pragma unroll
            for (int j=0;j<8;j++){ v[j] = cbc[k*EMBD + lane + j*32]; s += v[j]*v[j]; }
            s = warp_sum(s);
            float inv = 1.f/sqrtf(s + 1e-12f);
            #pragma unroll
            for (int j=0;j<8;j++){
                int d = lane + j*32;
                float nv = v[j]*inv;
                g_cl_n[k*EMBD + d] = nv;
                g_clT[d*KCLP + k]  = nv;
            }
            if (lane==0) g_bias_cl[k] = 0.f;
        } else {
            #pragma unroll
            for (int j=0;j<8;j++){
                int d = lane + j*32;
                g_cl_n[k*EMBD + d] = 0.f;
                g_clT[d*KCLP + k]  = 0.f;
            }
            if (lane==0) g_bias_cl[k] = -1e30f;   // padded code never wins
        }
    } else if (w < KCLP + 2*KCOS){
        int k = w - KCLP;                          // 0..4095 over [2,K,EMB]
        float v[8]; float s = 0.f;
        #pragma unroll
        for (int j=0;j<8;j++){ v[j] = cbcos[k*EMBD + lane + j*32]; s += v[j]*v[j]; }
        s = warp_sum(s);
        float inv = 1.f/sqrtf(s + 1e-12f);
        int q = k >> 11, kk = k & (KCOS-1);
        #pragma unroll
        for (int j=0;j<8;j++){
            int d = lane + j*32;
            float nv = v[j]*inv;
            g_cos_n[k*EMBD + d]             = nv;
            g_cosT[(q*EMBD + d)*KCOS + kk]  = nv;
        }
    } else if (w < KCLP + 2*KCOS + KCOS){
        int k = w - KCLP - 2*KCOS;
        float v[8]; float s = 0.f;
        #pragma unroll
        for (int j=0;j<8;j++){ v[j] = cbe[k*EMBD + lane + j*32]; s += v[j]*v[j]; }
        s = warp_sum(s);
        #pragma unroll
        for (int j=0;j<8;j++){
            int d = lane + j*32;
            g_eucT[d*KCOS + k] = v[j];
        }
        if (lane==0) g_bias_euc[k] = -0.5f*s;
    }
}

// ---------------- 128x128x16 f32x2 SGEMM + bias (+ ReLU) ----------------
// C[M,Nn] = act(A[M,Kk] @ B[Kk,Nn] + bias). M,Nn multiples of 128; Kk multiple of 16.
template<bool RELU>
__global__ __launch_bounds__(256)
void sgemm_bias(const float* __restrict__ A, const float* __restrict__ B,
                const float* __restrict__ bias, float* __restrict__ C,
                int Nn, int Kk){
    __shared__ __align__(16) float As[16][132];
    __shared__ __align__(16) float Bs[16][132];
    const int tid = threadIdx.x;
    const int tx = tid & 15, ty = tid >> 4;
    const int row0 = blockIdx.x * 128;
    const int col0 = blockIdx.y * 128;
    u64 acc[8][4];
    #pragma unroll
    for (int i=0;i<8;i++){
        #pragma unroll
        for (int j=0;j<4;j++) acc[i][j] = 0ull;
    }
    for (int kt=0; kt<Kk; kt+=16){
        #pragma unroll
        for (int li=tid; li<512; li+=256){
            int m = li >> 2, kq = li & 3;
            float4 v = *(const float4*)(A + (size_t)(row0+m)*Kk + kt + kq*4);
            As[kq*4+0][m]=v.x; As[kq*4+1][m]=v.y; As[kq*4+2][m]=v.z; As[kq*4+3][m]=v.w;
        }
        #pragma unroll
        for (int li=tid; li<512; li+=256){
            int k = li >> 5, n4 = li & 31;
            *(float4*)&Bs[k][n4*4] = *(const float4*)(B + (size_t)(kt+k)*Nn + col0 + n4*4);
        }
        __syncthreads();
        #pragma unroll
        for (int k=0;k<16;k++){
            float4 a0 = *(float4*)&As[k][ty*4];
            float4 a1 = *(float4*)&As[k][64 + ty*4];
            ulonglong2 b0 = *(ulonglong2*)&Bs[k][tx*4];
            ulonglong2 b1 = *(ulonglong2*)&Bs[k][64 + tx*4];
            u64 ad[8];
            ad[0]=pack2(a0.x); ad[1]=pack2(a0.y); ad[2]=pack2(a0.z); ad[3]=pack2(a0.w);
            ad[4]=pack2(a1.x); ad[5]=pack2(a1.y); ad[6]=pack2(a1.z); ad[7]=pack2(a1.w);
            #pragma unroll
            for (int i=0;i<8;i++){
                fma2(acc[i][0], ad[i], b0.x);
                fma2(acc[i][1], ad[i], b0.y);
                fma2(acc[i][2], ad[i], b1.x);
                fma2(acc[i][3], ad[i], b1.y);
            }
        }
        __syncthreads();
    }
    #pragma unroll
    for (int i=0;i<8;i++){
        int row = row0 + ((i<4) ? (ty*4+i) : (64 + ty*4 + i - 4));
        #pragma unroll
        for (int jp=0;jp<4;jp++){
            int col = col0 + ((jp<2) ? (tx*4 + jp*2) : (64 + tx*4 + (jp-2)*2));
            float2 v = unpack2(acc[i][jp]);
            v.x += bias[col]; v.y += bias[col+1];
            if (RELU){ v.x = fmaxf(v.x, 0.f); v.y = fmaxf(v.y, 0.f); }
            *(float2*)(C + (size_t)row*Nn + col) = v;
        }
    }
}

// ---------------- fused sim + argmax: score = X @ CT + bias, per-row argmax ----------------
// X [NROWS, EMBD]; CT [EMBD, NC] (transposed codes). Block: 128 rows x ALL codes.
__global__ __launch_bounds__(256)
void vq_argmax(const float* __restrict__ X, const float* __restrict__ CT,
               const float* __restrict__ bias, int NC, int* __restrict__ outidx){
    __shared__ __align__(16) float As[16][132];
    __shared__ __align__(16) float Bs[16][132];
    __shared__ float cbest[128][16];
    __shared__ int   cidx [128][16];
    const int tid = threadIdx.x;
    const int tx = tid & 15, ty = tid >> 4;
    const int row0 = blockIdx.x * 128;
    const float NEGINF = __int_as_float(0xff800000);
    float best[8]; int bidx[8];
    #pragma unroll
    for (int i=0;i<8;i++){ best[i] = NEGINF; bidx[i] = 0; }

    for (int ct=0; ct<NC; ct+=128){
        u64 acc[8][4];
        #pragma unroll
        for (int i=0;i<8;i++){
            #pragma unroll
            for (int j=0;j<4;j++) acc[i][j] = 0ull;
        }
        for (int kt=0; kt<EMBD; kt+=16){
            #pragma unroll
            for (int li=tid; li<512; li+=256){
                int m = li >> 2, kq = li & 3;
                float4 v = *(const float4*)(X + (size_t)(row0+m)*EMBD + kt + kq*4);
                As[kq*4+0][m]=v.x; As[kq*4+1][m]=v.y; As[kq*4+2][m]=v.z; As[kq*4+3][m]=v.w;
            }
            #pragma unroll
            for (int li=tid; li<512; li+=256){
                int k = li >> 5, n4 = li & 31;
                *(float4*)&Bs[k][n4*4] = *(const float4*)(CT + (size_t)(kt+k)*NC + ct + n4*4);
            }
            __syncthreads();
            #pragma unroll
            for (int k=0;k<16;k++){
                float4 a0 = *(float4*)&As[k][ty*4];
                float4 a1 = *(float4*)&As[k][64 + ty*4];
                ulonglong2 b0 = *(ulonglong2*)&Bs[k][tx*4];
                ulonglong2 b1 = *(ulonglong2*)&Bs[k][64 + tx*4];
                u64 ad[8];
                ad[0]=pack2(a0.x); ad[1]=pack2(a0.y); ad[2]=pack2(a0.z); ad[3]=pack2(a0.w);
                ad[4]=pack2(a1.x); ad[5]=pack2(a1.y); ad[6]=pack2(a1.z); ad[7]=pack2(a1.w);
                #pragma unroll
                for (int i=0;i<8;i++){
                    fma2(acc[i][0], ad[i], b0.x);
                    fma2(acc[i][1], ad[i], b0.y);
                    fma2(acc[i][2], ad[i], b1.x);
                    fma2(acc[i][3], ad[i], b1.y);
                }
            }
            __syncthreads();
        }
        // running argmax (strict > keeps the first/lowest index, matching jnp.argmax)
        #pragma unroll
        for (int i=0;i<8;i++){
            #pragma unroll
            for (int jp=0;jp<4;jp++){
                int col = ct + ((jp<2) ? (tx*4 + jp*2) : (64 + tx*4 + (jp-2)*2));
                float2 v = unpack2(acc[i][jp]);
                float s0 = v.x + bias[col];
                float s1 = v.y + bias[col+1];
                if (s0 > best[i]){ best[i]=s0; bidx[i]=col; }
                if (s1 > best[i]){ best[i]=s1; bidx[i]=col+1; }
            }
        }
    }
    __syncthreads();
    #pragma unroll
    for (int i=0;i<8;i++){
        int rl = (i<4) ? (ty*4+i) : (64 + ty*4 + i - 4);
        cbest[rl][tx] = best[i];
        cidx [rl][tx] = bidx[i];
    }
    __syncthreads();
    if (tid < 128){
        float b = NEGINF; int bi = 0x7fffffff;
        #pragma unroll
        for (int t=0;t<16;t++){
            float v = cbest[tid][t]; int id = cidx[tid][t];
            if (v > b || (v == b && id < bi)){ b = v; bi = id; }
        }
        outidx[row0 + tid] = bi;
    }
}

// ---------------- VQ stage updates (warp per row; 32 rows/block; 1024 blocks) ----------------
// Stage A (cluster, cosine): loss vs xn, r1 = res - q
__global__ __launch_bounds__(256)
void k_updateA(){
    const int lane = threadIdx.x & 31;
    const int wib  = threadIdx.x >> 5;
    float lsum = 0.f;
    #pragma unroll
    for (int rr=0; rr<4; rr++){
        int row = blockIdx.x*32 + wib*4 + rr;
        const float* x = g_res + (size_t)row*EMBD;
        float v[8]; float s = 0.f;
        #pragma unroll
        for (int j=0;j<8;j++){ v[j] = x[lane + j*32]; s += v[j]*v[j]; }
        s = warp_sum(s);
        float inv = 1.f/sqrtf(s + 1e-12f);
        const float* q = g_cl_n + (size_t)g_idx[row]*EMBD;
        float* r1 = g_r1 + (size_t)row*EMBD;
        #pragma unroll
        for (int j=0;j<8;j++){
            int d = lane + j*32;
            float qd = q[d];
            float df = qd - v[j]*inv;
            lsum += df*df;
            r1[d] = v[j] - qd;
        }
    }
    lsum = warp_sum(lsum);
    __shared__ float ws[8];
    if (lane==0) ws[wib] = lsum;
    __syncthreads();
    if (threadIdx.x==0){
        float t = 0.f;
        #pragma unroll
        for (int i=0;i<8;i++) t += ws[i];
        g_losspart[0*1024 + blockIdx.x] = t;
    }
}

// Cosine residual stages: second=0 -> r2 = X - q, rq = q ; second=1 -> rq += q, re = res - rq
__global__ __launch_bounds__(256)
void k_updateB(const float* __restrict__ X, const int* __restrict__ idxp,
               const float* __restrict__ cn, int second, int stage){
    const int lane = threadIdx.x & 31;
    const int wib  = threadIdx.x >> 5;
    float lsum = 0.f;
    #pragma unroll
    for (int rr=0; rr<4; rr++){
        int row = blockIdx.x*32 + wib*4 + rr;
        const float* xr = X + (size_t)row*EMBD;
        float v[8]; float s = 0.f;
        #pragma unroll
        for (int j=0;j<8;j++){ v[j] = xr[lane + j*32]; s += v[j]*v[j]; }
        s = warp_sum(s);
        float inv = 1.f/sqrtf(s + 1e-12f);
        const float* q = cn + (size_t)idxp[row]*EMBD;
        #pragma unroll
        for (int j=0;j<8;j++){
            int d = lane + j*32;
            size_t o = (size_t)row*EMBD + d;
            float qd = q[d];
            float df = qd - v[j]*inv;
            lsum += df*df;
            if (second == 0){
                g_r2[o] = v[j] - qd;
                g_rq[o] = qd;
            } else {
                float rq = g_rq[o] + qd;
                g_rq[o] = rq;
                g_re[o] = g_res[o] - rq;
            }
        }
    }
    lsum = warp_sum(lsum);
    __shared__ float ws[8];
    if (lane==0) ws[wib] = lsum;
    __syncthreads();
    if (threadIdx.x==0){
        float t = 0.f;
        #pragma unroll
        for (int i=0;i<8;i++) t += ws[i];
        g_losspart[stage*1024 + blockIdx.x] = t;
    }
}

// Euclid stage: loss vs raw x_e, out_rq = rq + q_e
__global__ __launch_bounds__(256)
void k_updateC(const float* __restrict__ cbe, float* __restrict__ out_rq){
    const int lane = threadIdx.x & 31;
    const int wib  = threadIdx.x >> 5;
    float lsum = 0.f;
    #pragma unroll
    for (int rr=0; rr<4; rr++){
        int row = blockIdx.x*32 + wib*4 + rr;
        int id = g_idx[3*NROWS + row];
        const float* q = cbe + (size_t)id*EMBD;
        #pragma unroll
        for (int j=0;j<8;j++){
            int d = lane + j*32;
            size_t o = (size_t)row*EMBD + d;
            float qd = q[d];
            float df = qd - g_re[o];
            lsum += df*df;
            out_rq[o] = g_rq[o] + qd;
        }
    }
    lsum = warp_sum(lsum);
    __shared__ float ws[8];
    if (lane==0) ws[wib] = lsum;
    __syncthreads();
    if (threadIdx.x==0){
        float t = 0.f;
        #pragma unroll
        for (int i=0;i<8;i++) t += ws[i];
        g_losspart[3*1024 + blockIdx.x] = t;
    }
}

// sem_ids [N,4] as float: (cluster, cos0, cos1, euclid)
__global__ void k_semwrite(float* __restrict__ out_ids){
    int t = blockIdx.x*blockDim.x + threadIdx.x;
    int row = t >> 2, s = t & 3;
    out_ids[t] = (float)g_idx[s*NROWS + row];
}

// total_loss = 10 * sum(losses), each loss = partial_sum / (N*EMB). Deterministic fixed tree.
__global__ void k_finalize(float* __restrict__ out){
    __shared__ float sh[256];
    int t = threadIdx.x;
    float s = 0.f;
    for (int st=0; st<4; st++)
        for (int b=t; b<1024; b+=256)
            s += g_losspart[st*1024 + b];
    sh[t] = s;
    __syncthreads();
    for (int o=128;o>0;o>>=1){
        if (t<o) sh[t] += sh[t+o];
        __syncthreads();
    }
    if (t==0) out[0] = 10.0f * sh[0] / (float)(NROWS*EMBD);
}

// ---------------- launch ----------------
// inputs: x, enc_w1, enc_b1, enc_w2, enc_b2, cb_cluster, cb_cos, cb_euc
// output layout (float32, return order): [total_loss(1)] [sem_ids N*4] [rq_embs N*256]
extern "C" void kernel_launch(void* const* d_in, const int* in_sizes, int n_in,
                              void* d_out, int out_size){
    const float* x     = (const float*)d_in[0];
    const float* w1    = (const float*)d_in[1];
    const float* b1    = (const float*)d_in[2];
    const float* w2    = (const float*)d_in[3];
    const float* b2    = (const float*)d_in[4];
    const float* cbc   = (const float*)d_in[5];
    const float* cbcos = (const float*)d_in[6];
    const float* cbe   = (const float*)d_in[7];
    float* out = (float*)d_out;

    void* p;
    float *ph, *pres, *pr1, *pr2, *pre, *pclT, *pbcl, *pcosT, *pbz, *peucT, *pbeuc, *pcosn;
    int* pidx;
    cudaGetSymbolAddress(&p, g_h);        ph    = (float*)p;
    cudaGetSymbolAddress(&p, g_res);      pres  = (float*)p;
    cudaGetSymbolAddress(&p, g_r1);       pr1   = (float*)p;
    cudaGetSymbolAddress(&p, g_r2);       pr2   = (float*)p;
    cudaGetSymbolAddress(&p, g_re);       pre   = (float*)p;
    cudaGetSymbolAddress(&p, g_clT);      pclT  = (float*)p;
    cudaGetSymbolAddress(&p, g_bias_cl);  pbcl  = (float*)p;
    cudaGetSymbolAddress(&p, g_cosT);     pcosT = (float*)p;
    cudaGetSymbolAddress(&p, g_bias_zero);pbz   = (float*)p;
    cudaGetSymbolAddress(&p, g_eucT);     peucT = (float*)p;
    cudaGetSymbolAddress(&p, g_bias_euc); pbeuc = (float*)p;
    cudaGetSymbolAddress(&p, g_cos_n);    pcosn = (float*)p;
    cudaGetSymbolAddress(&p, g_idx);      pidx  = (int*)p;

    // codebook prep (normalize + transpose + biases)
    prep_codes<<<784, 256>>>(cbc, cbcos, cbe);

    // encoder MLP
    sgemm_bias<true ><<<dim3(NROWS/128, HIDDIM/128), 256>>>(x,  w1, b1, ph,   HIDDIM, INDIM);
    sgemm_bias<false><<<dim3(NROWS/128, EMBD/128),   256>>>(ph, w2, b2, pres, EMBD,   HIDDIM);

    // stage 1: cluster VQ (cosine, padded to 128 codes)
    vq_argmax<<<NROWS/128, 256>>>(pres, pclT, pbcl, KCLP, pidx + 0*NROWS);
    k_updateA<<<1024, 256>>>();

    // stage 2: residual VQ, cosine quantizer 0
    vq_argmax<<<NROWS/128, 256>>>(pr1, pcosT, pbz, KCOS, pidx + 1*NROWS);
    k_updateB<<<1024, 256>>>(pr1, pidx + 1*NROWS, pcosn, 0, 1);

    // stage 3: residual VQ, cosine quantizer 1
    vq_argmax<<<NROWS/128, 256>>>(pr2, pcosT + EMBD*KCOS, pbz, KCOS, pidx + 2*NROWS);
    k_updateB<<<1024, 256>>>(pr2, pidx + 2*NROWS, pcosn + KCOS*EMBD, 1, 2);

    // stage 4: euclidean VQ (argmax of x.c - 0.5||c||^2)
    vq_argmax<<<NROWS/128, 256>>>(pre, peucT, pbeuc, KCOS, pidx + 3*NROWS);
    k_updateC<<<1024, 256>>>(cbe, out + 1 + 4*NROWS);

    // outputs
    k_semwrite<<<512, 256>>>(out + 1);
    k_finalize<<<1, 256>>>(out);
}